// round 15
// baseline (speedup 1.0000x reference)
#include <cuda_runtime.h>
#include <cuda_bf16.h>
#include <math.h>
#include <cstdint>
#include <mma.h>

using namespace nvcuda;

#define BB 4
#define CC 512
#define CQ 64
#define NN 4096

// Scratch (device globals; no runtime allocation allowed)
__device__ float g_Q[(size_t)BB * NN * CQ];           // [B][N][Cq] (pre-scaled by log2e)
__device__ float g_K[(size_t)BB * CQ * NN];           // [B][Cq][N]
__device__ __nv_bfloat16 g_V[(size_t)BB * CC * NN];   // [B][C][N] bf16
__device__ __nv_bfloat16 g_P[(size_t)BB * NN * NN];   // [B][N][N] bf16 exp(energy)
__device__ float g_L[(size_t)BB * NN];                // [B][N] row sums

__device__ __forceinline__ uint32_t smem_u32(const void* p) {
    uint32_t a;
    asm("{ .reg .u64 t; cvta.to.shared.u64 t, %1; cvt.u32.u64 %0, t; }"
        : "=r"(a) : "l"(p));
    return a;
}
__device__ __forceinline__ float fexp2(float x) {
    float y;
    asm("ex2.approx.f32 %0, %1;" : "=f"(y) : "f"(x));
    return y;
}
#define CP_ASYNC16(dst_u32, src_ptr) \
    asm volatile("cp.async.cg.shared.global [%0], [%1], 16;" \
                 :: "r"(dst_u32), "l"(src_ptr) : "memory")
#define CP_COMMIT() asm volatile("cp.async.commit_group;" ::: "memory")
#define CP_WAIT(n)  asm volatile("cp.async.wait_group %0;" :: "n"(n) : "memory")

#define ASTRIDE 40
#define BSTRIDE 136
#define EPST 132
#define LOG2E 1.4426950408889634f

#define NN_STAGE_FLOATS (128 * ASTRIDE + 32 * BSTRIDE)   // 9472
#define SMEM_NN_BYTES   (2 * NN_STAGE_FLOATS * 4)        // 75776

// qkproj (split): A tile 64x32, B tile 32x128
#define QK_STAGE_FLOATS (64 * ASTRIDE + 32 * BSTRIDE)    // 6912
#define SMEM_QK_BYTES   (2 * QK_STAGE_FLOATS * 4)        // 55296

// ===========================================================================
// Split Q/K projection (tf32 MMA): blockIdx.y = 0 -> Q (transposed, *log2e),
// blockIdx.y = 1 -> K. M=64 tile, 256 blocks total -> fills the chip.
// ===========================================================================
__global__ void __launch_bounds__(256, 2)
qkproj_kernel(const float* __restrict__ Wq, const float* __restrict__ Wk,
              const float* __restrict__ X,
              float* __restrict__ Q, float* __restrict__ K,
              float* __restrict__ L) {
    extern __shared__ float sm[];

    const int b  = blockIdx.z;
    const int isK = blockIdx.y;
    const int n0 = blockIdx.x * 128;
    const float* W  = isK ? Wk : Wq;
    const float* Bb = X + (size_t)b * CC * NN + n0;

    const int tid = threadIdx.x;
    const int wid = tid >> 5;
    const int wm = wid >> 2;   // 0..1 -> m offset wm*32
    const int wn = wid & 3;    // 0..3 -> n offset wn*32

    if (!isK && tid < 128) L[(size_t)b * NN + n0 + tid] = 0.0f;

    wmma::fragment<wmma::accumulator, 16, 16, 8, float> acc[2][2];
    #pragma unroll
    for (int f = 0; f < 2; f++)
        #pragma unroll
        for (int g = 0; g < 2; g++)
            wmma::fill_fragment(acc[f][g], 0.0f);

    const uint32_t smb = smem_u32(sm);

    auto issue = [&](int k0, int s) {
        const uint32_t as_u = smb + (uint32_t)(s * QK_STAGE_FLOATS) * 4;
        const uint32_t bs_u = as_u + 64 * ASTRIDE * 4;
        #pragma unroll
        for (int k = 0; k < 2; k++) {          // A: 64 rows x 8 segs = 512
            int t = tid + k * 256;
            int row = t >> 3, seg = t & 7;
            CP_ASYNC16(as_u + (uint32_t)(row * ASTRIDE + seg * 4) * 4,
                       W + (size_t)row * CC + k0 + seg * 4);
        }
        #pragma unroll
        for (int k = 0; k < 4; k++) {          // B: 32 rows x 32 segs = 1024
            int t = tid + k * 256;
            int row = t >> 5, seg = t & 31;
            CP_ASYNC16(bs_u + (uint32_t)(row * BSTRIDE + seg * 4) * 4,
                       Bb + (size_t)(k0 + row) * NN + seg * 4);
        }
        CP_COMMIT();
    };

    issue(0, 0);

    const int nchunks = CC >> 5;   // 16
    for (int c = 0; c < nchunks; c++) {
        const int s = c & 1;
        if (c + 1 < nchunks) { issue((c + 1) << 5, s ^ 1); CP_WAIT(1); }
        else                 { CP_WAIT(0); }
        __syncthreads();

        const float* As = sm + s * QK_STAGE_FLOATS;
        const float* Bs = As + 64 * ASTRIDE;

        #pragma unroll
        for (int kk = 0; kk < 4; kk++) {
            wmma::fragment<wmma::matrix_a, 16, 16, 8, wmma::precision::tf32, wmma::row_major> af[2];
            wmma::fragment<wmma::matrix_b, 16, 16, 8, wmma::precision::tf32, wmma::row_major> bf[2];
            #pragma unroll
            for (int f = 0; f < 2; f++)
                wmma::load_matrix_sync(af[f], As + (wm * 32 + f * 16) * ASTRIDE + kk * 8, ASTRIDE);
            #pragma unroll
            for (int g = 0; g < 2; g++)
                wmma::load_matrix_sync(bf[g], Bs + kk * 8 * BSTRIDE + wn * 32 + g * 16, BSTRIDE);
            #pragma unroll
            for (int f = 0; f < 2; f++)
                #pragma unroll
                for (int g = 0; g < 2; g++)
                    wmma::mma_sync(acc[f][g], af[f], bf[g], acc[f][g]);
        }
        __syncthreads();
    }

    float* Ep = sm;    // 64 x EPST
    #pragma unroll
    for (int f = 0; f < 2; f++)
        #pragma unroll
        for (int g = 0; g < 2; g++)
            wmma::store_matrix_sync(Ep + (wm * 32 + f * 16) * EPST + wn * 32 + g * 16,
                                    acc[f][g], EPST, wmma::mem_row_major);
    __syncthreads();

    if (isK) {
        // K: coalesced fp32 row-major stores, 64 rows x 128 cols
        float* Kb = K + (size_t)b * CQ * NN + n0;
        #pragma unroll
        for (int k = 0; k < 8; k++) {
            int t = tid + k * 256;
            int r = t >> 5, sc = t & 31;
            float4 v = *(const float4*)(Ep + r * EPST + sc * 4);
            *(float4*)(Kb + (size_t)r * NN + sc * 4) = v;
        }
    } else {
        // Q: transposed stores Q[n][o], pre-scaled by log2e
        float* Qb = Q + (size_t)b * NN * CQ;
        #pragma unroll
        for (int k = 0; k < 2; k++) {
            int t = tid + k * 256;
            int r = t & 63, cg = t >> 6;   // cg in 0..7
            #pragma unroll
            for (int c2 = 0; c2 < 16; c2++) {
                int n = cg * 16 + c2;
                Qb[(size_t)(n0 + n) * CQ + r] = Ep[r * EPST + n] * LOG2E;
            }
        }
    }
}

// ===========================================================================
// Heterogeneous kernel: blockIdx.y < 4 -> V projection tile,
//                       blockIdx.y >= 4 -> energy (E'=Q'K, exp2, bf16 P, l).
// ===========================================================================
__global__ void __launch_bounds__(256, 2)
ev_kernel(const float* __restrict__ Q, const float* __restrict__ K,
          __nv_bfloat16* __restrict__ P, float* __restrict__ l,
          const float* __restrict__ Wv, const float* __restrict__ X,
          __nv_bfloat16* __restrict__ V) {
    extern __shared__ float sm[];

    const int b   = blockIdx.z;
    const int tid = threadIdx.x;
    const int wid = tid >> 5;
    const int lane = tid & 31;
    const int wm = wid >> 1;
    const int wn = wid & 1;
    const uint32_t smb = smem_u32(sm);

    if (blockIdx.y < 4) {
        // ---------------- V projection tile ----------------
        const int m0 = blockIdx.y * 128;
        const int n0 = blockIdx.x * 128;
        const float* Ab = Wv + (size_t)m0 * CC;
        const float* Bb = X + (size_t)b * CC * NN + n0;

        wmma::fragment<wmma::accumulator, 16, 16, 8, float> acc[2][4];
        #pragma unroll
        for (int f = 0; f < 2; f++)
            #pragma unroll
            for (int g = 0; g < 4; g++)
                wmma::fill_fragment(acc[f][g], 0.0f);

        auto issue = [&](int k0, int s) {
            const uint32_t as_u = smb + (uint32_t)(s * NN_STAGE_FLOATS) * 4;
            const uint32_t bs_u = as_u + 128 * ASTRIDE * 4;
            #pragma unroll
            for (int k = 0; k < 4; k++) {
                int t = tid + k * 256;
                int row = t >> 3, seg = t & 7;
                CP_ASYNC16(as_u + (uint32_t)(row * ASTRIDE + seg * 4) * 4,
                           Ab + (size_t)row * CC + k0 + seg * 4);
            }
            #pragma unroll
            for (int k = 0; k < 4; k++) {
                int t = tid + k * 256;
                int row = t >> 5, seg = t & 31;
                CP_ASYNC16(bs_u + (uint32_t)(row * BSTRIDE + seg * 4) * 4,
                           Bb + (size_t)(k0 + row) * NN + seg * 4);
            }
            CP_COMMIT();
        };

        issue(0, 0);
        const int nchunks = CC >> 5;
        for (int c = 0; c < nchunks; c++) {
            const int s = c & 1;
            if (c + 1 < nchunks) { issue((c + 1) << 5, s ^ 1); CP_WAIT(1); }
            else                 { CP_WAIT(0); }
            __syncthreads();

            const float* As = sm + s * NN_STAGE_FLOATS;
            const float* Bs = As + 128 * ASTRIDE;

            #pragma unroll
            for (int kk = 0; kk < 4; kk++) {
                wmma::fragment<wmma::matrix_a, 16, 16, 8, wmma::precision::tf32, wmma::row_major> af[2];
                wmma::fragment<wmma::matrix_b, 16, 16, 8, wmma::precision::tf32, wmma::row_major> bf[4];
                #pragma unroll
                for (int f = 0; f < 2; f++)
                    wmma::load_matrix_sync(af[f], As + (wm * 32 + f * 16) * ASTRIDE + kk * 8, ASTRIDE);
                #pragma unroll
                for (int g = 0; g < 4; g++)
                    wmma::load_matrix_sync(bf[g], Bs + kk * 8 * BSTRIDE + wn * 64 + g * 16, BSTRIDE);
                #pragma unroll
                for (int f = 0; f < 2; f++)
                    #pragma unroll
                    for (int g = 0; g < 4; g++)
                        wmma::mma_sync(acc[f][g], af[f], bf[g], acc[f][g]);
            }
            __syncthreads();
        }

        float* Ep = sm;
        #pragma unroll
        for (int f = 0; f < 2; f++)
            #pragma unroll
            for (int g = 0; g < 4; g++)
                wmma::store_matrix_sync(Ep + (wm * 32 + f * 16) * EPST + wn * 64 + g * 16,
                                        acc[f][g], EPST, wmma::mem_row_major);
        __syncthreads();

        __nv_bfloat16* Vb = V + ((size_t)b * CC + m0) * NN + n0;
        #pragma unroll
        for (int t = tid; t < 128 * 32; t += 256) {
            int r = t >> 5, sc = t & 31;
            float4 a = *(const float4*)(Ep + r * EPST + sc * 4);
            __nv_bfloat162 w0 = __float22bfloat162_rn(make_float2(a.x, a.y));
            __nv_bfloat162 w1 = __float22bfloat162_rn(make_float2(a.z, a.w));
            uint2 u = make_uint2(*(uint32_t*)&w0, *(uint32_t*)&w1);
            *(uint2*)(Vb + (size_t)r * NN + sc * 4) = u;
        }
    } else {
        // ---------------- energy tile ----------------
        const int i0 = (blockIdx.y - 4) * 128;
        const int j0b = blockIdx.x * 128;
        const float* Qb = Q + ((size_t)b * NN + i0) * CQ;
        const float* Kb = K + (size_t)b * CQ * NN + j0b;

        wmma::fragment<wmma::accumulator, 16, 16, 8, float> acc[2][4];
        #pragma unroll
        for (int f = 0; f < 2; f++)
            #pragma unroll
            for (int g = 0; g < 4; g++)
                wmma::fill_fragment(acc[f][g], 0.0f);

        auto issue = [&](int k0, int s) {
            const uint32_t as_u = smb + (uint32_t)(s * NN_STAGE_FLOATS) * 4;
            const uint32_t bs_u = as_u + 128 * ASTRIDE * 4;
            #pragma unroll
            for (int k = 0; k < 4; k++) {
                int t = tid + k * 256;
                int row = t >> 3, seg = t & 7;
                CP_ASYNC16(as_u + (uint32_t)(row * ASTRIDE + seg * 4) * 4,
                           Qb + (size_t)row * CQ + k0 + seg * 4);
            }
            #pragma unroll
            for (int k = 0; k < 4; k++) {
                int t = tid + k * 256;
                int row = t >> 5, seg = t & 31;
                CP_ASYNC16(bs_u + (uint32_t)(row * BSTRIDE + seg * 4) * 4,
                           Kb + (size_t)(k0 + row) * NN + seg * 4);
            }
            CP_COMMIT();
        };

        issue(0, 0);
        #pragma unroll
        for (int c = 0; c < 2; c++) {
            if (c == 0) { issue(32, 1); CP_WAIT(1); }
            else        { CP_WAIT(0); }
            __syncthreads();

            const float* As = sm + c * NN_STAGE_FLOATS;
            const float* Bs = As + 128 * ASTRIDE;

            #pragma unroll
            for (int kk = 0; kk < 4; kk++) {
                wmma::fragment<wmma::matrix_a, 16, 16, 8, wmma::precision::tf32, wmma::row_major> af[2];
                wmma::fragment<wmma::matrix_b, 16, 16, 8, wmma::precision::tf32, wmma::row_major> bf[4];
                #pragma unroll
                for (int f = 0; f < 2; f++)
                    wmma::load_matrix_sync(af[f], As + (wm * 32 + f * 16) * ASTRIDE + kk * 8, ASTRIDE);
                #pragma unroll
                for (int g = 0; g < 4; g++)
                    wmma::load_matrix_sync(bf[g], Bs + kk * 8 * BSTRIDE + wn * 64 + g * 16, BSTRIDE);
                #pragma unroll
                for (int f = 0; f < 2; f++)
                    #pragma unroll
                    for (int g = 0; g < 4; g++)
                        wmma::mma_sync(acc[f][g], af[f], bf[g], acc[f][g]);
            }
            __syncthreads();
        }

        float* Ep = sm;
        #pragma unroll
        for (int f = 0; f < 2; f++)
            #pragma unroll
            for (int g = 0; g < 4; g++) {
                #pragma unroll
                for (int e = 0; e < acc[f][g].num_elements; e++)
                    acc[f][g].x[e] = fexp2(acc[f][g].x[e]);
                wmma::store_matrix_sync(Ep + (wm * 32 + f * 16) * EPST + wn * 64 + g * 16,
                                        acc[f][g], EPST, wmma::mem_row_major);
            }
        __syncthreads();

        __nv_bfloat16* Pbase = P + (size_t)b * NN * NN + (size_t)i0 * NN + j0b;
        float* lb = l + (size_t)b * NN + i0;
        #pragma unroll
        for (int k = 0; k < 16; k++) {
            const int r = wid + k * 8;
            float4 v = *(const float4*)(Ep + r * EPST + lane * 4);
            __nv_bfloat162 w0 = __float22bfloat162_rn(make_float2(v.x, v.y));
            __nv_bfloat162 w1 = __float22bfloat162_rn(make_float2(v.z, v.w));
            uint2 u = make_uint2(*(uint32_t*)&w0, *(uint32_t*)&w1);
            *(uint2*)(Pbase + (size_t)r * NN + lane * 4) = u;

            float s = (v.x + v.y) + (v.z + v.w);
            #pragma unroll
            for (int o = 16; o > 0; o >>= 1)
                s += __shfl_xor_sync(0xffffffffu, s, o);
            if (lane == 0)
                atomicAdd(lb + r, s);
        }
    }
}

// ===========================================================================
// Out GEMM (bf16 m16n16k16, NT) + fused normalize/gamma/residual.
// Tile 128(c) x 128(i), 256 threads, 3-stage cp.async, 2 CTAs/SM
// (221KB smem total; acc[2][4] = 64 regs fits (256,2) without spills).
// ===========================================================================
#define OT_M 128
#define OT_N 128
#define KC 64
#define HST 72
#define OT_STAGE_HALVES ((OT_M + OT_N) * HST)            // 18432
#define SMEM_OUT_BYTES  (3 * OT_STAGE_HALVES * 2)        // 110592

__global__ void __launch_bounds__(256, 2)
wmma_out_kernel(const __nv_bfloat16* __restrict__ V,
                const __nv_bfloat16* __restrict__ P,
                const float* __restrict__ x, const float* __restrict__ gamma,
                const float* __restrict__ l, float* __restrict__ out) {
    extern __shared__ float smf[];
    __nv_bfloat16* smh = (__nv_bfloat16*)smf;

    const int b  = blockIdx.z;
    const int c0 = blockIdx.x * OT_M;
    const int i0 = blockIdx.y * OT_N;
    const __nv_bfloat16* Vb = V + ((size_t)b * CC + c0) * NN;
    const __nv_bfloat16* Pb = P + ((size_t)b * NN + i0) * NN;

    const int tid = threadIdx.x;
    const int wid = tid >> 5;
    const int wm = wid >> 1;   // 0..3 -> m offset wm*32
    const int wn = wid & 1;    // 0..1 -> n offset wn*64

    wmma::fragment<wmma::accumulator, 16, 16, 16, float> acc[2][4];
    #pragma unroll
    for (int f = 0; f < 2; f++)
        #pragma unroll
        for (int g = 0; g < 4; g++)
            wmma::fill_fragment(acc[f][g], 0.0f);

    const uint32_t smb = smem_u32(smh);

    auto issue = [&](int j0, int s) {
        const uint32_t as_u = smb + (uint32_t)(s * OT_STAGE_HALVES) * 2;
        const uint32_t bs_u = as_u + OT_M * HST * 2;
        #pragma unroll
        for (int k = 0; k < 4; k++) {          // A: 128 rows x 8 segs = 1024
            int t = tid + k * 256;
            int row = t >> 3, seg = t & 7;
            CP_ASYNC16(as_u + (uint32_t)(row * HST + seg * 8) * 2,
                       Vb + (size_t)row * NN + j0 + seg * 8);
        }
        #pragma unroll
        for (int k = 0; k < 4; k++) {          // B: 128 rows x 8 segs = 1024
            int t = tid + k * 256;
            int row = t >> 3, seg = t & 7;
            CP_ASYNC16(bs_u + (uint32_t)(row * HST + seg * 8) * 2,
                       Pb + (size_t)row * NN + j0 + seg * 8);
        }
        CP_COMMIT();
    };

    issue(0, 0);
    issue(KC, 1);

    const int nchunks = NN / KC;   // 64
    for (int c = 0; c < nchunks; c++) {
        if (c + 2 < nchunks) { issue((c + 2) * KC, (c + 2) % 3); CP_WAIT(2); }
        else if (c + 1 < nchunks) { CP_WAIT(1); }
        else { CP_WAIT(0); }
        __syncthreads();

        const __nv_bfloat16* As = smh + (c % 3) * OT_STAGE_HALVES;
        const __nv_bfloat16* Bs = As + OT_M * HST;

        #pragma unroll
        for (int kk = 0; kk < KC / 16; kk++) {
            wmma::fragment<wmma::matrix_a, 16, 16, 16, __nv_bfloat16, wmma::row_major> af[2];
            wmma::fragment<wmma::matrix_b, 16, 16, 16, __nv_bfloat16, wmma::col_major> bf[4];
            #pragma unroll
            for (int f = 0; f < 2; f++)
                wmma::load_matrix_sync(af[f], As + (wm * 32 + f * 16) * HST + kk * 16, HST);
            #pragma unroll
            for (int g = 0; g < 4; g++)
                wmma::load_matrix_sync(bf[g], Bs + (wn * 64 + g * 16) * HST + kk * 16, HST);
            #pragma unroll
            for (int f = 0; f < 2; f++)
                #pragma unroll
                for (int g = 0; g < 4; g++)
                    wmma::mma_sync(acc[f][g], af[f], bf[g], acc[f][g]);
        }
        __syncthreads();
    }

    // Epilogue: stage fp32 (128x132 = 67.6KB fits in 110KB), fused normalize.
    float* Ep = smf;
    float* linv = smf + OT_M * EPST;
    #pragma unroll
    for (int f = 0; f < 2; f++)
        #pragma unroll
        for (int g = 0; g < 4; g++)
            wmma::store_matrix_sync(Ep + (wm * 32 + f * 16) * EPST + wn * 64 + g * 16,
                                    acc[f][g], EPST, wmma::mem_row_major);
    if (tid < 128)
        linv[tid] = 1.0f / l[(size_t)b * NN + i0 + tid];
    __syncthreads();

    const float gm = gamma[0];
    #pragma unroll
    for (int t = tid; t < OT_M * 32; t += 256) {
        int r = t >> 5, sc = t & 31;
        float4 a = *(const float4*)(Ep + r * EPST + sc * 4);
        size_t gi = ((size_t)b * CC + c0 + r) * NN + i0 + sc * 4;
        float4 xv = *(const float4*)(x + gi);
        float4 o;
        o.x = gm * a.x * linv[sc * 4 + 0] + xv.x;
        o.y = gm * a.y * linv[sc * 4 + 1] + xv.y;
        o.z = gm * a.z * linv[sc * 4 + 2] + xv.z;
        o.w = gm * a.w * linv[sc * 4 + 3] + xv.w;
        *(float4*)(out + gi) = o;
    }
}

// ---------------------------------------------------------------------------
extern "C" void kernel_launch(void* const* d_in, const int* in_sizes, int n_in,
                              void* d_out, int out_size) {
    const float* x     = (const float*)d_in[0];
    const float* Wq    = (const float*)d_in[1];
    const float* Wk    = (const float*)d_in[2];
    const float* Wv    = (const float*)d_in[3];
    const float* gamma = (const float*)d_in[4];
    float* out = (float*)d_out;

    float *Q, *K, *L;
    __nv_bfloat16 *V, *P;
    cudaGetSymbolAddress((void**)&Q, g_Q);
    cudaGetSymbolAddress((void**)&K, g_K);
    cudaGetSymbolAddress((void**)&V, g_V);
    cudaGetSymbolAddress((void**)&P, g_P);
    cudaGetSymbolAddress((void**)&L, g_L);

    cudaFuncSetAttribute(qkproj_kernel,
                         cudaFuncAttributeMaxDynamicSharedMemorySize, SMEM_QK_BYTES);
    cudaFuncSetAttribute(ev_kernel,
                         cudaFuncAttributeMaxDynamicSharedMemorySize, SMEM_NN_BYTES);
    cudaFuncSetAttribute(wmma_out_kernel,
                         cudaFuncAttributeMaxDynamicSharedMemorySize, SMEM_OUT_BYTES);

    // Q/K projections (split blocks; Q pre-scaled by log2e) + L zeroing
    qkproj_kernel<<<dim3(NN / 128, 2, BB), 256, SMEM_QK_BYTES>>>(Wq, Wk, x, Q, K, L);

    // Heterogeneous launch: y<4 = vproj tiles, y>=4 = energy tiles
    ev_kernel<<<dim3(NN / 128, 4 + NN / 128, BB), 256, SMEM_NN_BYTES>>>(
        Q, K, P, L, Wv, x, V);

    // Out GEMM + fused normalize/gamma/residual (128x128, 3-stage, 2 CTAs/SM)
    wmma_out_kernel<<<dim3(CC / OT_M, NN / OT_N, BB), 256, SMEM_OUT_BYTES>>>(
        V, P, x, gamma, L, out);
}

// round 16
// speedup vs baseline: 1.5600x; 1.5600x over previous
#include <cuda_runtime.h>
#include <cuda_bf16.h>
#include <math.h>
#include <cstdint>
#include <mma.h>

using namespace nvcuda;

#define BB 4
#define CC 512
#define CQ 64
#define NN 4096

// Scratch (device globals; no runtime allocation allowed)
__device__ float g_Q[(size_t)BB * NN * CQ];           // [B][N][Cq] (pre-scaled by log2e)
__device__ float g_K[(size_t)BB * CQ * NN];           // [B][Cq][N]
__device__ __nv_bfloat16 g_V[(size_t)BB * CC * NN];   // [B][C][N] bf16
__device__ __nv_bfloat16 g_P[(size_t)BB * NN * NN];   // [B][N][N] bf16 exp(energy)
__device__ float g_L[(size_t)BB * NN];                // [B][N] row sums

__device__ __forceinline__ uint32_t smem_u32(const void* p) {
    uint32_t a;
    asm("{ .reg .u64 t; cvta.to.shared.u64 t, %1; cvt.u32.u64 %0, t; }"
        : "=r"(a) : "l"(p));
    return a;
}
__device__ __forceinline__ float fexp2(float x) {
    float y;
    asm("ex2.approx.f32 %0, %1;" : "=f"(y) : "f"(x));
    return y;
}
#define CP_ASYNC16(dst_u32, src_ptr) \
    asm volatile("cp.async.cg.shared.global [%0], [%1], 16;" \
                 :: "r"(dst_u32), "l"(src_ptr) : "memory")
#define CP_COMMIT() asm volatile("cp.async.commit_group;" ::: "memory")
#define CP_WAIT(n)  asm volatile("cp.async.wait_group %0;" :: "n"(n) : "memory")

#define ASTRIDE 40
#define BSTRIDE 136
#define EPST 132
#define LOG2E 1.4426950408889634f

#define NN_STAGE_FLOATS (128 * ASTRIDE + 32 * BSTRIDE)   // 9472
#define SMEM_NN_BYTES   (2 * NN_STAGE_FLOATS * 4)        // 75776

// ===========================================================================
// Fused Q+K projection (tf32 MMA) + L zeroing.  Q stored pre-scaled by log2e.
// ===========================================================================
__global__ void __launch_bounds__(256, 2)
qkproj_kernel(const float* __restrict__ Wq, const float* __restrict__ Wk,
              const float* __restrict__ X,
              float* __restrict__ Q, float* __restrict__ K,
              float* __restrict__ L) {
    extern __shared__ float sm[];

    const int b  = blockIdx.z;
    const int n0 = blockIdx.x * 128;
    const float* Bb = X + (size_t)b * CC * NN + n0;

    const int tid = threadIdx.x;
    const int wid = tid >> 5;
    const int wm = wid >> 1;
    const int wn = wid & 1;

    if (tid < 128) L[(size_t)b * NN + n0 + tid] = 0.0f;

    wmma::fragment<wmma::accumulator, 16, 16, 8, float> acc[2][4];
    #pragma unroll
    for (int f = 0; f < 2; f++)
        #pragma unroll
        for (int g = 0; g < 4; g++)
            wmma::fill_fragment(acc[f][g], 0.0f);

    const uint32_t smb = smem_u32(sm);

    auto issue = [&](int k0, int s) {
        const uint32_t as_u = smb + (uint32_t)(s * NN_STAGE_FLOATS) * 4;
        const uint32_t bs_u = as_u + 128 * ASTRIDE * 4;
        #pragma unroll
        for (int k = 0; k < 4; k++) {
            int t = tid + k * 256;
            int row = t >> 3, seg = t & 7;
            const float* src = (row < 64)
                ? Wq + (size_t)row * CC + k0 + seg * 4
                : Wk + (size_t)(row - 64) * CC + k0 + seg * 4;
            CP_ASYNC16(as_u + (uint32_t)(row * ASTRIDE + seg * 4) * 4, src);
        }
        #pragma unroll
        for (int k = 0; k < 4; k++) {
            int t = tid + k * 256;
            int row = t >> 5, seg = t & 31;
            CP_ASYNC16(bs_u + (uint32_t)(row * BSTRIDE + seg * 4) * 4,
                       Bb + (size_t)(k0 + row) * NN + seg * 4);
        }
        CP_COMMIT();
    };

    issue(0, 0);

    const int nchunks = CC >> 5;   // 16
    for (int c = 0; c < nchunks; c++) {
        const int s = c & 1;
        if (c + 1 < nchunks) { issue((c + 1) << 5, s ^ 1); CP_WAIT(1); }
        else                 { CP_WAIT(0); }
        __syncthreads();

        const float* As = sm + s * NN_STAGE_FLOATS;
        const float* Bs = As + 128 * ASTRIDE;

        #pragma unroll
        for (int kk = 0; kk < 4; kk++) {
            wmma::fragment<wmma::matrix_a, 16, 16, 8, wmma::precision::tf32, wmma::row_major> af[2];
            wmma::fragment<wmma::matrix_b, 16, 16, 8, wmma::precision::tf32, wmma::row_major> bf[4];
            #pragma unroll
            for (int f = 0; f < 2; f++)
                wmma::load_matrix_sync(af[f], As + (wm * 32 + f * 16) * ASTRIDE + kk * 8, ASTRIDE);
            #pragma unroll
            for (int g = 0; g < 4; g++)
                wmma::load_matrix_sync(bf[g], Bs + kk * 8 * BSTRIDE + wn * 64 + g * 16, BSTRIDE);
            #pragma unroll
            for (int f = 0; f < 2; f++)
                #pragma unroll
                for (int g = 0; g < 4; g++)
                    wmma::mma_sync(acc[f][g], af[f], bf[g], acc[f][g]);
        }
        __syncthreads();
    }

    float* Ep = sm;
    #pragma unroll
    for (int f = 0; f < 2; f++)
        #pragma unroll
        for (int g = 0; g < 4; g++)
            wmma::store_matrix_sync(Ep + (wm * 32 + f * 16) * EPST + wn * 64 + g * 16,
                                    acc[f][g], EPST, wmma::mem_row_major);
    __syncthreads();

    // K half (rows 64-127): coalesced fp32 row-major stores
    float* Kb = K + (size_t)b * CQ * NN + n0;
    #pragma unroll
    for (int k = 0; k < 8; k++) {
        int t = tid + k * 256;
        int r = t >> 5, sc = t & 31;
        float4 v = *(const float4*)(Ep + (64 + r) * EPST + sc * 4);
        *(float4*)(Kb + (size_t)r * NN + sc * 4) = v;
    }
    // Q half (rows 0-63): transposed stores Q[n][o], pre-scaled by log2e
    float* Qb = Q + (size_t)b * NN * CQ;
    #pragma unroll
    for (int k = 0; k < 4; k++) {
        int t = tid + k * 256;
        int r = t & 63, cg = t >> 6;
        #pragma unroll
        for (int c2 = 0; c2 < 8; c2++) {
            int n = cg * 8 + c2;
            Qb[(size_t)(n0 + n) * CQ + r] = Ep[r * EPST + n] * LOG2E;
        }
    }
}

// ===========================================================================
// Heterogeneous kernel: blockIdx.y < 4 -> V projection tile,
//                       blockIdx.y >= 4 -> energy (E'=Q'K, exp2, bf16 P, l).
// ===========================================================================
__global__ void __launch_bounds__(256, 2)
ev_kernel(const float* __restrict__ Q, const float* __restrict__ K,
          __nv_bfloat16* __restrict__ P, float* __restrict__ l,
          const float* __restrict__ Wv, const float* __restrict__ X,
          __nv_bfloat16* __restrict__ V) {
    extern __shared__ float sm[];

    const int b   = blockIdx.z;
    const int tid = threadIdx.x;
    const int wid = tid >> 5;
    const int lane = tid & 31;
    const int wm = wid >> 1;
    const int wn = wid & 1;
    const uint32_t smb = smem_u32(sm);

    if (blockIdx.y < 4) {
        // ---------------- V projection tile ----------------
        const int m0 = blockIdx.y * 128;
        const int n0 = blockIdx.x * 128;
        const float* Ab = Wv + (size_t)m0 * CC;
        const float* Bb = X + (size_t)b * CC * NN + n0;

        wmma::fragment<wmma::accumulator, 16, 16, 8, float> acc[2][4];
        #pragma unroll
        for (int f = 0; f < 2; f++)
            #pragma unroll
            for (int g = 0; g < 4; g++)
                wmma::fill_fragment(acc[f][g], 0.0f);

        auto issue = [&](int k0, int s) {
            const uint32_t as_u = smb + (uint32_t)(s * NN_STAGE_FLOATS) * 4;
            const uint32_t bs_u = as_u + 128 * ASTRIDE * 4;
            #pragma unroll
            for (int k = 0; k < 4; k++) {
                int t = tid + k * 256;
                int row = t >> 3, seg = t & 7;
                CP_ASYNC16(as_u + (uint32_t)(row * ASTRIDE + seg * 4) * 4,
                           Ab + (size_t)row * CC + k0 + seg * 4);
            }
            #pragma unroll
            for (int k = 0; k < 4; k++) {
                int t = tid + k * 256;
                int row = t >> 5, seg = t & 31;
                CP_ASYNC16(bs_u + (uint32_t)(row * BSTRIDE + seg * 4) * 4,
                           Bb + (size_t)(k0 + row) * NN + seg * 4);
            }
            CP_COMMIT();
        };

        issue(0, 0);
        const int nchunks = CC >> 5;
        for (int c = 0; c < nchunks; c++) {
            const int s = c & 1;
            if (c + 1 < nchunks) { issue((c + 1) << 5, s ^ 1); CP_WAIT(1); }
            else                 { CP_WAIT(0); }
            __syncthreads();

            const float* As = sm + s * NN_STAGE_FLOATS;
            const float* Bs = As + 128 * ASTRIDE;

            #pragma unroll
            for (int kk = 0; kk < 4; kk++) {
                wmma::fragment<wmma::matrix_a, 16, 16, 8, wmma::precision::tf32, wmma::row_major> af[2];
                wmma::fragment<wmma::matrix_b, 16, 16, 8, wmma::precision::tf32, wmma::row_major> bf[4];
                #pragma unroll
                for (int f = 0; f < 2; f++)
                    wmma::load_matrix_sync(af[f], As + (wm * 32 + f * 16) * ASTRIDE + kk * 8, ASTRIDE);
                #pragma unroll
                for (int g = 0; g < 4; g++)
                    wmma::load_matrix_sync(bf[g], Bs + kk * 8 * BSTRIDE + wn * 64 + g * 16, BSTRIDE);
                #pragma unroll
                for (int f = 0; f < 2; f++)
                    #pragma unroll
                    for (int g = 0; g < 4; g++)
                        wmma::mma_sync(acc[f][g], af[f], bf[g], acc[f][g]);
            }
            __syncthreads();
        }

        float* Ep = sm;
        #pragma unroll
        for (int f = 0; f < 2; f++)
            #pragma unroll
            for (int g = 0; g < 4; g++)
                wmma::store_matrix_sync(Ep + (wm * 32 + f * 16) * EPST + wn * 64 + g * 16,
                                        acc[f][g], EPST, wmma::mem_row_major);
        __syncthreads();

        __nv_bfloat16* Vb = V + ((size_t)b * CC + m0) * NN + n0;
        #pragma unroll
        for (int t = tid; t < 128 * 32; t += 256) {
            int r = t >> 5, sc = t & 31;
            float4 a = *(const float4*)(Ep + r * EPST + sc * 4);
            __nv_bfloat162 w0 = __float22bfloat162_rn(make_float2(a.x, a.y));
            __nv_bfloat162 w1 = __float22bfloat162_rn(make_float2(a.z, a.w));
            uint2 u = make_uint2(*(uint32_t*)&w0, *(uint32_t*)&w1);
            *(uint2*)(Vb + (size_t)r * NN + sc * 4) = u;
        }
    } else {
        // ---------------- energy tile ----------------
        const int i0 = (blockIdx.y - 4) * 128;
        const int j0b = blockIdx.x * 128;
        const float* Qb = Q + ((size_t)b * NN + i0) * CQ;
        const float* Kb = K + (size_t)b * CQ * NN + j0b;

        wmma::fragment<wmma::accumulator, 16, 16, 8, float> acc[2][4];
        #pragma unroll
        for (int f = 0; f < 2; f++)
            #pragma unroll
            for (int g = 0; g < 4; g++)
                wmma::fill_fragment(acc[f][g], 0.0f);

        auto issue = [&](int k0, int s) {
            const uint32_t as_u = smb + (uint32_t)(s * NN_STAGE_FLOATS) * 4;
            const uint32_t bs_u = as_u + 128 * ASTRIDE * 4;
            #pragma unroll
            for (int k = 0; k < 4; k++) {
                int t = tid + k * 256;
                int row = t >> 3, seg = t & 7;
                CP_ASYNC16(as_u + (uint32_t)(row * ASTRIDE + seg * 4) * 4,
                           Qb + (size_t)row * CQ + k0 + seg * 4);
            }
            #pragma unroll
            for (int k = 0; k < 4; k++) {
                int t = tid + k * 256;
                int row = t >> 5, seg = t & 31;
                CP_ASYNC16(bs_u + (uint32_t)(row * BSTRIDE + seg * 4) * 4,
                           Kb + (size_t)(k0 + row) * NN + seg * 4);
            }
            CP_COMMIT();
        };

        issue(0, 0);
        #pragma unroll
        for (int c = 0; c < 2; c++) {
            if (c == 0) { issue(32, 1); CP_WAIT(1); }
            else        { CP_WAIT(0); }
            __syncthreads();

            const float* As = sm + c * NN_STAGE_FLOATS;
            const float* Bs = As + 128 * ASTRIDE;

            #pragma unroll
            for (int kk = 0; kk < 4; kk++) {
                wmma::fragment<wmma::matrix_a, 16, 16, 8, wmma::precision::tf32, wmma::row_major> af[2];
                wmma::fragment<wmma::matrix_b, 16, 16, 8, wmma::precision::tf32, wmma::row_major> bf[4];
                #pragma unroll
                for (int f = 0; f < 2; f++)
                    wmma::load_matrix_sync(af[f], As + (wm * 32 + f * 16) * ASTRIDE + kk * 8, ASTRIDE);
                #pragma unroll
                for (int g = 0; g < 4; g++)
                    wmma::load_matrix_sync(bf[g], Bs + kk * 8 * BSTRIDE + wn * 64 + g * 16, BSTRIDE);
                #pragma unroll
                for (int f = 0; f < 2; f++)
                    #pragma unroll
                    for (int g = 0; g < 4; g++)
                        wmma::mma_sync(acc[f][g], af[f], bf[g], acc[f][g]);
            }
            __syncthreads();
        }

        float* Ep = sm;
        #pragma unroll
        for (int f = 0; f < 2; f++)
            #pragma unroll
            for (int g = 0; g < 4; g++) {
                #pragma unroll
                for (int e = 0; e < acc[f][g].num_elements; e++)
                    acc[f][g].x[e] = fexp2(acc[f][g].x[e]);
                wmma::store_matrix_sync(Ep + (wm * 32 + f * 16) * EPST + wn * 64 + g * 16,
                                        acc[f][g], EPST, wmma::mem_row_major);
            }
        __syncthreads();

        __nv_bfloat16* Pbase = P + (size_t)b * NN * NN + (size_t)i0 * NN + j0b;
        float* lb = l + (size_t)b * NN + i0;
        #pragma unroll
        for (int k = 0; k < 16; k++) {
            const int r = wid + k * 8;
            float4 v = *(const float4*)(Ep + r * EPST + lane * 4);
            __nv_bfloat162 w0 = __float22bfloat162_rn(make_float2(v.x, v.y));
            __nv_bfloat162 w1 = __float22bfloat162_rn(make_float2(v.z, v.w));
            uint2 u = make_uint2(*(uint32_t*)&w0, *(uint32_t*)&w1);
            *(uint2*)(Pbase + (size_t)r * NN + lane * 4) = u;

            float s = (v.x + v.y) + (v.z + v.w);
            #pragma unroll
            for (int o = 16; o > 0; o >>= 1)
                s += __shfl_xor_sync(0xffffffffu, s, o);
            if (lane == 0)
                atomicAdd(lb + r, s);
        }
    }
}

// ===========================================================================
// Out GEMM (bf16 m16n16k16, NT) + fused normalize/gamma/residual.
// Tile 128(c) x 128(i), 256 threads (8 warps, 4m x 2n, warp tile 32x64),
// 2-stage cp.async, 2 CTAs/SM (acc 64 regs -> fits (256,2) without spills).
// ===========================================================================
#define OT_M 128
#define OT_N 128
#define KC 64
#define HST 72
#define OT_STAGE_HALVES ((OT_M + OT_N) * HST)            // 18432
#define SMEM_OUT_BYTES  (2 * OT_STAGE_HALVES * 2)        // 73728

__global__ void __launch_bounds__(256, 2)
wmma_out_kernel(const __nv_bfloat16* __restrict__ V,
                const __nv_bfloat16* __restrict__ P,
                const float* __restrict__ x, const float* __restrict__ gamma,
                const float* __restrict__ l, float* __restrict__ out) {
    extern __shared__ float smf[];
    __nv_bfloat16* smh = (__nv_bfloat16*)smf;

    const int b  = blockIdx.z;
    const int c0 = blockIdx.x * OT_M;
    const int i0 = blockIdx.y * OT_N;
    const __nv_bfloat16* Vb = V + ((size_t)b * CC + c0) * NN;
    const __nv_bfloat16* Pb = P + ((size_t)b * NN + i0) * NN;

    const int tid = threadIdx.x;
    const int wid = tid >> 5;
    const int wm = wid >> 1;   // 0..3 -> m offset wm*32
    const int wn = wid & 1;    // 0..1 -> n offset wn*64

    wmma::fragment<wmma::accumulator, 16, 16, 16, float> acc[2][4];
    #pragma unroll
    for (int f = 0; f < 2; f++)
        #pragma unroll
        for (int g = 0; g < 4; g++)
            wmma::fill_fragment(acc[f][g], 0.0f);

    const uint32_t smb = smem_u32(smh);

    auto issue = [&](int j0, int s) {
        const uint32_t as_u = smb + (uint32_t)(s * OT_STAGE_HALVES) * 2;
        const uint32_t bs_u = as_u + OT_M * HST * 2;
        #pragma unroll
        for (int k = 0; k < 4; k++) {          // A: 128 rows x 8 segs = 1024
            int t = tid + k * 256;
            int row = t >> 3, seg = t & 7;
            CP_ASYNC16(as_u + (uint32_t)(row * HST + seg * 8) * 2,
                       Vb + (size_t)row * NN + j0 + seg * 8);
        }
        #pragma unroll
        for (int k = 0; k < 4; k++) {          // B: 128 rows x 8 segs = 1024
            int t = tid + k * 256;
            int row = t >> 3, seg = t & 7;
            CP_ASYNC16(bs_u + (uint32_t)(row * HST + seg * 8) * 2,
                       Pb + (size_t)row * NN + j0 + seg * 8);
        }
        CP_COMMIT();
    };

    issue(0, 0);

    const int nchunks = NN / KC;   // 64
    for (int c = 0; c < nchunks; c++) {
        const int s = c & 1;
        if (c + 1 < nchunks) { issue((c + 1) * KC, s ^ 1); CP_WAIT(1); }
        else                 { CP_WAIT(0); }
        __syncthreads();

        const __nv_bfloat16* As = smh + s * OT_STAGE_HALVES;
        const __nv_bfloat16* Bs = As + OT_M * HST;

        #pragma unroll
        for (int kk = 0; kk < KC / 16; kk++) {
            wmma::fragment<wmma::matrix_a, 16, 16, 16, __nv_bfloat16, wmma::row_major> af[2];
            wmma::fragment<wmma::matrix_b, 16, 16, 16, __nv_bfloat16, wmma::col_major> bf[4];
            #pragma unroll
            for (int f = 0; f < 2; f++)
                wmma::load_matrix_sync(af[f], As + (wm * 32 + f * 16) * HST + kk * 16, HST);
            #pragma unroll
            for (int g = 0; g < 4; g++)
                wmma::load_matrix_sync(bf[g], Bs + (wn * 64 + g * 16) * HST + kk * 16, HST);
            #pragma unroll
            for (int f = 0; f < 2; f++)
                #pragma unroll
                for (int g = 0; g < 4; g++)
                    wmma::mma_sync(acc[f][g], af[f], bf[g], acc[f][g]);
        }
        __syncthreads();
    }

    // Epilogue: stage fp32 (128x132 = 67.6KB fits in 72KB), fused normalize.
    float* Ep = smf;
    float* linv = smf + OT_M * EPST;
    #pragma unroll
    for (int f = 0; f < 2; f++)
        #pragma unroll
        for (int g = 0; g < 4; g++)
            wmma::store_matrix_sync(Ep + (wm * 32 + f * 16) * EPST + wn * 64 + g * 16,
                                    acc[f][g], EPST, wmma::mem_row_major);
    if (tid < 128)
        linv[tid] = 1.0f / l[(size_t)b * NN + i0 + tid];
    __syncthreads();

    const float gm = gamma[0];
    #pragma unroll
    for (int t = tid; t < OT_M * 32; t += 256) {
        int r = t >> 5, sc = t & 31;
        float4 a = *(const float4*)(Ep + r * EPST + sc * 4);
        size_t gi = ((size_t)b * CC + c0 + r) * NN + i0 + sc * 4;
        float4 xv = *(const float4*)(x + gi);
        float4 o;
        o.x = gm * a.x * linv[sc * 4 + 0] + xv.x;
        o.y = gm * a.y * linv[sc * 4 + 1] + xv.y;
        o.z = gm * a.z * linv[sc * 4 + 2] + xv.z;
        o.w = gm * a.w * linv[sc * 4 + 3] + xv.w;
        *(float4*)(out + gi) = o;
    }
}

// ---------------------------------------------------------------------------
extern "C" void kernel_launch(void* const* d_in, const int* in_sizes, int n_in,
                              void* d_out, int out_size) {
    const float* x     = (const float*)d_in[0];
    const float* Wq    = (const float*)d_in[1];
    const float* Wk    = (const float*)d_in[2];
    const float* Wv    = (const float*)d_in[3];
    const float* gamma = (const float*)d_in[4];
    float* out = (float*)d_out;

    float *Q, *K, *L;
    __nv_bfloat16 *V, *P;
    cudaGetSymbolAddress((void**)&Q, g_Q);
    cudaGetSymbolAddress((void**)&K, g_K);
    cudaGetSymbolAddress((void**)&V, g_V);
    cudaGetSymbolAddress((void**)&P, g_P);
    cudaGetSymbolAddress((void**)&L, g_L);

    cudaFuncSetAttribute(qkproj_kernel,
                         cudaFuncAttributeMaxDynamicSharedMemorySize, SMEM_NN_BYTES);
    cudaFuncSetAttribute(ev_kernel,
                         cudaFuncAttributeMaxDynamicSharedMemorySize, SMEM_NN_BYTES);
    cudaFuncSetAttribute(wmma_out_kernel,
                         cudaFuncAttributeMaxDynamicSharedMemorySize, SMEM_OUT_BYTES);

    // Q+K projections + L zeroing (Q pre-scaled by log2e)
    qkproj_kernel<<<dim3(NN / 128, 1, BB), 256, SMEM_NN_BYTES>>>(Wq, Wk, x, Q, K, L);

    // Heterogeneous launch: y<4 = vproj tiles, y>=4 = energy tiles
    ev_kernel<<<dim3(NN / 128, 4 + NN / 128, BB), 256, SMEM_NN_BYTES>>>(
        Q, K, P, L, Wv, x, V);

    // Out GEMM + fused normalize/gamma/residual (128x128, 2-stage, 2 CTAs/SM)
    wmma_out_kernel<<<dim3(CC / OT_M, NN / OT_N, BB), 256, SMEM_OUT_BYTES>>>(
        V, P, x, gamma, L, out);
}